// round 10
// baseline (speedup 1.0000x reference)
#include <cuda_runtime.h>
#include <cstdint>

#define M_TOTAL 32768
#define E_DIM 2048
#define L_DIM 64
#define H_DIM 128
#define S_LEN 4096

// Scratch (device globals: allocation-free rule)
__device__ float g_qT[(size_t)H_DIM * M_TOTAL];   // q transposed [col][m], tf32-rna
__device__ float g_k[(size_t)M_TOTAL * H_DIM];
__device__ float g_v[(size_t)M_TOTAL * H_DIM];

// Pre-rounded (tf32-rna) weights, same layouts as inputs:
#define WR_DKV 0
#define WR_Q   (2048 * 64)
#define WR_K   (WR_Q + 2048 * 128)
#define WR_V   (WR_K + 64 * 128)
#define WR_TOT (WR_V + 64 * 128)
__device__ float g_wr[WR_TOT];

// ---------------- tf32 / async helpers ----------------

__device__ __forceinline__ void mma_tf32(float* d, const uint32_t* a, const uint32_t* b) {
    asm volatile(
        "mma.sync.aligned.m16n8k8.row.col.f32.tf32.tf32.f32 "
        "{%0,%1,%2,%3}, {%4,%5,%6,%7}, {%8,%9}, {%0,%1,%2,%3};\n"
        : "+f"(d[0]), "+f"(d[1]), "+f"(d[2]), "+f"(d[3])
        : "r"(a[0]), "r"(a[1]), "r"(a[2]), "r"(a[3]), "r"(b[0]), "r"(b[1]));
}

__device__ __forceinline__ uint32_t to_tf32(float x) {
    uint32_t h;
    asm("cvt.rna.tf32.f32 %0, %1;" : "=r"(h) : "f"(x));
    return h;
}

// non-hoistable global load (bits)
__device__ __forceinline__ uint32_t ldg_u32(const float* p) {
    uint32_t r;
    asm volatile("ld.global.nc.b32 %0, [%1];" : "=r"(r) : "l"(p));
    return r;
}

__device__ __forceinline__ void cp16(void* dst, const void* src) {
    uint32_t d = (uint32_t)__cvta_generic_to_shared(dst);
    asm volatile("cp.async.cg.shared.global [%0], [%1], 16;\n" :: "r"(d), "l"(src));
}
#define CP_COMMIT asm volatile("cp.async.commit_group;\n")
#define CP_WAIT0  asm volatile("cp.async.wait_group 0;\n")
#define CP_WAIT1  asm volatile("cp.async.wait_group 1;\n")
#define CP_WAIT2  asm volatile("cp.async.wait_group 2;\n")

// ---------------- weight pre-rounding (once per call, ~5us) ----------------

__global__ void prep_w(const float* __restrict__ w_dkv, const float* __restrict__ w_q,
                       const float* __restrict__ w_k, const float* __restrict__ w_v) {
    int i = blockIdx.x * 256 + threadIdx.x;
    float v;
    if (i < WR_Q)       v = w_dkv[i];
    else if (i < WR_K)  v = w_q[i - WR_Q];
    else if (i < WR_V)  v = w_k[i - WR_K];
    else                v = w_v[i - WR_V];
    g_wr[i] = __uint_as_float(to_tf32(v));
}

// ---------------- 3-stage pipelined 1xTF32 GEMM ----------------
// C = A[M,K] @ concat(B1[K,N1], B2[K,N2]); B pre-rounded tf32 in gmem;
// A rna-rounded at fragment load. BM=64, KT=32, 256 threads = 8 warps 2(m)x4(n).
// round_c: rna-round outputs (C1 scaled by c1s). c2t: store C2 transposed
// ([col][M_TOTAL], rna-rounded) — used for q.

template <int BN>
__global__ void __launch_bounds__(256, 2) gemm_kernel(
    const float* __restrict__ A,
    const float* __restrict__ B1, const float* __restrict__ B2,
    float* __restrict__ C1, float* __restrict__ C2,
    int K, int N1, int N2, int round_c, float c1s, int c2t)
{
    constexpr int BM = 64;
    constexpr int KTL = 32;
    constexpr int WNT = BN / 32;
    constexpr int ASTR = KTL + 4;           // 36
    constexpr int BSTR = BN + 8;
    constexpr int ASZ = BM * ASTR;
    constexpr int BSZ = KTL * BSTR;
    constexpr int BUF = ASZ + BSZ;

    extern __shared__ float sh[];

    const int tid = threadIdx.x;
    const int warp = tid >> 5, lane = tid & 31;
    const int wm = warp >> 2;
    const int wn = warp & 3;
    const int lr = lane >> 2, lc = lane & 3;
    const int m0 = blockIdx.y * BM;
    const int n0 = blockIdx.x * BN;

    const int arow = tid >> 2;              // 0..63
    const int ac4 = (tid & 3) * 4;          // 0,4,8,12 (+16)

    float acc[2][WNT][4];
#pragma unroll
    for (int mt = 0; mt < 2; mt++)
#pragma unroll
        for (int nt = 0; nt < WNT; nt++)
#pragma unroll
            for (int j = 0; j < 4; j++) acc[mt][nt][j] = 0.f;

    const int nk = K / KTL;

    auto stage = [&](int kt) {
        float* As = sh + (kt % 3) * BUF;
        float* Bs = As + ASZ;
        int kb = kt * KTL;
        cp16(&As[arow * ASTR + ac4],      A + (size_t)(m0 + arow) * K + kb + ac4);
        cp16(&As[arow * ASTR + ac4 + 16], A + (size_t)(m0 + arow) * K + kb + ac4 + 16);
        constexpr int NB = (KTL * BN / 4) / 256;
#pragma unroll
        for (int it = 0; it < NB; it++) {
            int i = it * 256 + tid;
            int brow = i / (BN / 4);
            int bc4 = (i % (BN / 4)) * 4;
            int gc = n0 + bc4;
            const float* src = (gc < N1) ? (B1 + (size_t)(kb + brow) * N1 + gc)
                                         : (B2 + (size_t)(kb + brow) * N2 + (gc - N1));
            cp16(&Bs[brow * BSTR + bc4], src);
        }
        CP_COMMIT;
    };

    stage(0);
    if (nk > 1) stage(1);

    for (int kt = 0; kt < nk; kt++) {
        if (kt + 2 < nk) { stage(kt + 2); CP_WAIT2; }
        else if (kt + 1 < nk) CP_WAIT1;
        else CP_WAIT0;
        __syncthreads();

        const float* As = sh + (kt % 3) * BUF;
        const float* Bs = As + ASZ;

#pragma unroll
        for (int ks = 0; ks < 4; ks++) {
            uint32_t ah[2][4];
#pragma unroll
            for (int mt = 0; mt < 2; mt++) {
                int rb = wm * 32 + mt * 16;
                ah[mt][0] = to_tf32(As[(rb + lr) * ASTR + ks * 8 + lc]);
                ah[mt][1] = to_tf32(As[(rb + lr + 8) * ASTR + ks * 8 + lc]);
                ah[mt][2] = to_tf32(As[(rb + lr) * ASTR + ks * 8 + lc + 4]);
                ah[mt][3] = to_tf32(As[(rb + lr + 8) * ASTR + ks * 8 + lc + 4]);
            }
#pragma unroll
            for (int nt = 0; nt < WNT; nt++) {
                int c0 = wn * (BN / 4) + nt * 8 + lr;
                uint32_t bh[2];
                bh[0] = __float_as_uint(Bs[(ks * 8 + lc) * BSTR + c0]);
                bh[1] = __float_as_uint(Bs[(ks * 8 + lc + 4) * BSTR + c0]);
#pragma unroll
                for (int mt = 0; mt < 2; mt++)
                    mma_tf32(acc[mt][nt], ah[mt], bh);
            }
        }
        __syncthreads();
    }

#pragma unroll
    for (int mt = 0; mt < 2; mt++) {
        int r0 = m0 + wm * 32 + mt * 16 + lr;
#pragma unroll
        for (int nt = 0; nt < WNT; nt++) {
            int gc = n0 + wn * (BN / 4) + nt * 8 + lc * 2;
            float o0 = acc[mt][nt][0], o1 = acc[mt][nt][1];
            float o2 = acc[mt][nt][2], o3 = acc[mt][nt][3];
            if (gc >= N1 && c2t) {
                // transposed + rna-rounded store (q)
                size_t base = (size_t)(gc - N1) * M_TOTAL;
                C2[base + r0]               = __uint_as_float(to_tf32(o0));
                C2[base + M_TOTAL + r0]     = __uint_as_float(to_tf32(o1));
                C2[base + r0 + 8]           = __uint_as_float(to_tf32(o2));
                C2[base + M_TOTAL + r0 + 8] = __uint_as_float(to_tf32(o3));
            } else {
                float* dst;
                int stride, col;
                float cs = 1.f;
                if (gc < N1) { dst = C1; stride = N1; col = gc; cs = c1s; }
                else         { dst = C2; stride = N2; col = gc - N1; }
                if (round_c) {
                    o0 = __uint_as_float(to_tf32(o0 * cs));
                    o1 = __uint_as_float(to_tf32(o1 * cs));
                    o2 = __uint_as_float(to_tf32(o2 * cs));
                    o3 = __uint_as_float(to_tf32(o3 * cs));
                }
                *(float2*)(dst + (size_t)r0 * stride + col)       = make_float2(o0, o1);
                *(float2*)(dst + (size_t)(r0 + 8) * stride + col) = make_float2(o2, o3);
            }
        }
    }
}

// ---------------- Flash attention (causal), 3 CTAs/SM ----------------
// BLOCK_M=64, 4 warps = (wm: 32-row half) x (wn: 32-kv half QK / 64-head half PV).
// No q state in regs/smem: q fragments fetched per-tile from qT (tf32-rna,
// transposed -> full-sector LDGs) via non-hoistable asm loads with 4-step
// prefetch. K/V staged by cp.async; P aliases Ks; softmax exp2-domain with
// cross-warp smem exchange (separate m / rs buffers).

constexpr int AKS = 132;
constexpr int AVS = 136;
constexpr int APS = 68;                  // P stride (aliased in Ks region)
constexpr int VOFF  = 64 * AKS;          // 8448
constexpr int XMOFF = VOFF + 64 * AVS;   // 17152 (m exchange, 128 floats)
constexpr int XROFF = XMOFF + 128;       // 17280 (rs exchange, 128 floats)
constexpr int ATTN_SMEM_BYTES = (XROFF + 128) * 4;   // 69632

__global__ void __launch_bounds__(128, 3) attn_kernel(
    const float* __restrict__ qT, const float* __restrict__ k,
    const float* __restrict__ v, float* __restrict__ out)
{
    extern __shared__ float sm[];
    float* Ks = sm;                 // K tile; aliased as P (stride APS)
    float* Vs = sm + VOFF;
    float* Xm = sm + XMOFF;
    float* Xr = sm + XROFF;

    const int idx = blockIdx.x;
    const int b = idx & 7;
    const int qb = 63 - (idx >> 3);         // longest first
    const int tid = threadIdx.x;
    const int warp = tid >> 5, lane = tid & 31;
    const int lr = lane >> 2, lc = lane & 3;
    const int wm = warp >> 1;               // row half (32 rows)
    const int wn = warp & 1;                // kv half (QK) / head half (PV)

    const float* kB = k + (size_t)b * S_LEN * H_DIM;
    const float* vB = v + (size_t)b * S_LEN * H_DIM;

    // global m row of this thread's fragment rows (mt0 base)
    const int gm = b * S_LEN + qb * 64 + wm * 32 + lr;

    float acc[2][8][4];
#pragma unroll
    for (int mt = 0; mt < 2; mt++)
#pragma unroll
        for (int nt = 0; nt < 8; nt++)
#pragma unroll
            for (int j = 0; j < 4; j++) acc[mt][nt][j] = 0.f;
    float mrow[2][2] = {{-INFINITY, -INFINITY}, {-INFINITY, -INFINITY}};
    float lrow[2][2] = {{0.f, 0.f}, {0.f, 0.f}};

    const int row64 = tid >> 5;
    const int c4 = (tid & 31) * 4;

    // q fragment prefetch pipeline: slot = ks % 5, 8 bits-regs per slot
    // [0..3]=mt0 (rows gm, gm+8), [4..7]=mt1 (rows gm+16, gm+24)
    uint32_t qfa[5][8];
    auto qload = [&](int slot, int ks) {
        const float* p0 = qT + (size_t)(ks * 8 + lc) * M_TOTAL + gm;
        const float* p1 = qT + (size_t)(ks * 8 + lc + 4) * M_TOTAL + gm;
        qfa[slot][0] = ldg_u32(p0);
        qfa[slot][1] = ldg_u32(p0 + 8);
        qfa[slot][2] = ldg_u32(p1);
        qfa[slot][3] = ldg_u32(p1 + 8);
        qfa[slot][4] = ldg_u32(p0 + 16);
        qfa[slot][5] = ldg_u32(p0 + 24);
        qfa[slot][6] = ldg_u32(p1 + 16);
        qfa[slot][7] = ldg_u32(p1 + 24);
    };

    for (int kv = 0; kv <= qb; kv++) {
        __syncthreads();  // (1) previous tile fully consumed

        // stage K,V tile (64 x 128 each)
#pragma unroll
        for (int rnd = 0; rnd < 16; rnd++) {
            int row = row64 + rnd * 4;
            cp16(&Ks[row * AKS + c4], kB + (size_t)(kv * 64 + row) * H_DIM + c4);
            cp16(&Vs[row * AVS + c4], vB + (size_t)(kv * 64 + row) * H_DIM + c4);
        }
        CP_COMMIT;

        // prefetch q frags for ks 0..3 (latency hidden under staging wait)
#pragma unroll
        for (int pk = 0; pk < 4; pk++) qload(pk, pk);

        CP_WAIT0;
        __syncthreads();  // (2) tiles ready

        // ---- S = q @ k^T : rows 32*wm (2mt) x kv cols 32*wn (4nt), 1xTF32 ----
        float sc[2][4][4];
#pragma unroll
        for (int mt = 0; mt < 2; mt++)
#pragma unroll
            for (int nt = 0; nt < 4; nt++)
#pragma unroll
                for (int j = 0; j < 4; j++) sc[mt][nt][j] = 0.f;

#pragma unroll
        for (int ks = 0; ks < 16; ks++) {
            if (ks < 12) qload((ks + 4) % 5, ks + 4);
#pragma unroll
            for (int nt = 0; nt < 4; nt++) {
                int kr = wn * 32 + nt * 8 + lr;
                uint32_t bh[2];
                bh[0] = __float_as_uint(Ks[kr * AKS + ks * 8 + lc]);
                bh[1] = __float_as_uint(Ks[kr * AKS + ks * 8 + lc + 4]);
                mma_tf32(sc[0][nt], &qfa[ks % 5][0], bh);
                mma_tf32(sc[1][nt], &qfa[ks % 5][4], bh);
            }
        }

        // Diagonal-block causal mask (tile-local coords)
        if (kv == qb) {
#pragma unroll
            for (int mt = 0; mt < 2; mt++)
#pragma unroll
                for (int nt = 0; nt < 4; nt++)
#pragma unroll
                    for (int j = 0; j < 4; j++) {
                        int col = wn * 32 + nt * 8 + lc * 2 + (j & 1);
                        int row = wm * 32 + mt * 16 + lr + (j >> 1) * 8;
                        if (col > row) sc[mt][nt][j] = -INFINITY;
                    }
        }

        // ---- online softmax (exp2 domain, cross-warp over wn) ----
        float mnew[2][2] = {{-INFINITY, -INFINITY}, {-INFINITY, -INFINITY}};
#pragma unroll
        for (int mt = 0; mt < 2; mt++)
#pragma unroll
            for (int nt = 0; nt < 4; nt++)
#pragma unroll
                for (int j = 0; j < 4; j++)
                    mnew[mt][j >> 1] = fmaxf(mnew[mt][j >> 1], sc[mt][nt][j]);
#pragma unroll
        for (int off = 1; off < 4; off <<= 1)
#pragma unroll
            for (int mt = 0; mt < 2; mt++) {
                mnew[mt][0] = fmaxf(mnew[mt][0], __shfl_xor_sync(0xffffffffu, mnew[mt][0], off));
                mnew[mt][1] = fmaxf(mnew[mt][1], __shfl_xor_sync(0xffffffffu, mnew[mt][1], off));
            }
        if (lc == 0) {
#pragma unroll
            for (int mt = 0; mt < 2; mt++)
#pragma unroll
                for (int h = 0; h < 2; h++)
                    Xm[((wm * 2 + wn) * 4 + mt * 2 + h) * 8 + lr] = mnew[mt][h];
        }
        __syncthreads();  // (3) m-exchange (also: all QK K-reads complete)

        float alpha[2][2];
#pragma unroll
        for (int mt = 0; mt < 2; mt++)
#pragma unroll
            for (int h = 0; h < 2; h++) {
                float mo = Xm[((wm * 2 + (1 - wn)) * 4 + mt * 2 + h) * 8 + lr];
                float mt_ = fmaxf(fmaxf(mrow[mt][h], mnew[mt][h]), mo);
                alpha[mt][h] = exp2f(mrow[mt][h] - mt_);
                mrow[mt][h] = mt_;
            }

        float rs[2][2] = {{0.f, 0.f}, {0.f, 0.f}};
#pragma unroll
        for (int mt = 0; mt < 2; mt++)
#pragma unroll
            for (int nt = 0; nt < 4; nt++)
#pragma unroll
                for (int j = 0; j < 4; j++) {
                    float p = exp2f(sc[mt][nt][j] - mrow[mt][j >> 1]);
                    sc[mt][nt][j] = p;
                    rs[mt][j >> 1] += p;
                }
#pragma unroll
        for (int off = 1; off < 4; off <<= 1)
#pragma unroll
            for (int mt = 0; mt < 2; mt++) {
                rs[mt][0] += __shfl_xor_sync(0xffffffffu, rs[mt][0], off);
                rs[mt][1] += __shfl_xor_sync(0xffffffffu, rs[mt][1], off);
            }

        // write P (rna) into dead Ks region; write rs partials
#pragma unroll
        for (int mt = 0; mt < 2; mt++)
#pragma unroll
            for (int nt = 0; nt < 4; nt++)
#pragma unroll
                for (int j = 0; j < 4; j++) {
                    int row = wm * 32 + mt * 16 + lr + (j >> 1) * 8;
                    int col = wn * 32 + nt * 8 + lc * 2 + (j & 1);
                    Ks[row * APS + col] = __uint_as_float(to_tf32(sc[mt][nt][j]));
                }
        if (lc == 0) {
#pragma unroll
            for (int mt = 0; mt < 2; mt++)
#pragma unroll
                for (int h = 0; h < 2; h++)
                    Xr[((wm * 2 + wn) * 4 + mt * 2 + h) * 8 + lr] = rs[mt][h];
        }
        __syncthreads();  // (4) P + rs ready

#pragma unroll
        for (int mt = 0; mt < 2; mt++)
#pragma unroll
            for (int h = 0; h < 2; h++) {
                float ro = Xr[((wm * 2 + (1 - wn)) * 4 + mt * 2 + h) * 8 + lr];
                lrow[mt][h] = lrow[mt][h] * alpha[mt][h] + rs[mt][h] + ro;
            }

#pragma unroll
        for (int mt = 0; mt < 2; mt++)
#pragma unroll
            for (int nt = 0; nt < 8; nt++) {
                acc[mt][nt][0] *= alpha[mt][0]; acc[mt][nt][1] *= alpha[mt][0];
                acc[mt][nt][2] *= alpha[mt][1]; acc[mt][nt][3] *= alpha[mt][1];
            }

        // ---- O += P @ V : rows 32*wm (2mt) x head cols 64*wn (8nt2), 1xTF32 ----
#pragma unroll
        for (int ks2 = 0; ks2 < 8; ks2++) {
            uint32_t pa[2][4];
#pragma unroll
            for (int mt = 0; mt < 2; mt++) {
                int base = wm * 32 + mt * 16;
                pa[mt][0] = __float_as_uint(Ks[(base + lr) * APS + ks2 * 8 + lc]);
                pa[mt][1] = __float_as_uint(Ks[(base + lr + 8) * APS + ks2 * 8 + lc]);
                pa[mt][2] = __float_as_uint(Ks[(base + lr) * APS + ks2 * 8 + lc + 4]);
                pa[mt][3] = __float_as_uint(Ks[(base + lr + 8) * APS + ks2 * 8 + lc + 4]);
            }
#pragma unroll
            for (int nt2 = 0; nt2 < 8; nt2++) {
                int vc = wn * 64 + nt2 * 8 + lr;
                uint32_t vb[2];
                vb[0] = __float_as_uint(Vs[(ks2 * 8 + lc) * AVS + vc]);
                vb[1] = __float_as_uint(Vs[(ks2 * 8 + lc + 4) * AVS + vc]);
                mma_tf32(acc[0][nt2], pa[0], vb);
                mma_tf32(acc[1][nt2], pa[1], vb);
            }
        }
    }

    // Epilogue
#pragma unroll
    for (int mt = 0; mt < 2; mt++) {
        float inv0 = 1.f / lrow[mt][0];
        float inv1 = 1.f / lrow[mt][1];
        size_t rowg = (size_t)gm + mt * 16;
#pragma unroll
        for (int nt2 = 0; nt2 < 8; nt2++) {
            int col = wn * 64 + nt2 * 8 + lc * 2;
            *(float2*)(out + rowg * H_DIM + col) =
                make_float2(acc[mt][nt2][0] * inv0, acc[mt][nt2][1] * inv0);
            *(float2*)(out + (rowg + 8) * H_DIM + col) =
                make_float2(acc[mt][nt2][2] * inv1, acc[mt][nt2][3] * inv1);
        }
    }
}

// ---------------- launch ----------------

extern "C" void kernel_launch(void* const* d_in, const int* in_sizes, int n_in,
                              void* d_out, int out_size) {
    const float* x     = (const float*)d_in[0];
    const float* w_dkv = (const float*)d_in[1];
    const float* w_k   = (const float*)d_in[2];
    const float* w_v   = (const float*)d_in[3];
    const float* w_q   = (const float*)d_in[4];

    float* out = (float*)d_out;                          // [B,S,HEAD]
    float* latent = out + (size_t)M_TOTAL * H_DIM;       // [B,S,LATENT]

    float *qTp, *kp, *vp, *wr;
    cudaGetSymbolAddress((void**)&qTp, g_qT);
    cudaGetSymbolAddress((void**)&kp, g_k);
    cudaGetSymbolAddress((void**)&vp, g_v);
    cudaGetSymbolAddress((void**)&wr, g_wr);

    constexpr int SMEM1 = 3 * (64 * 36 + 32 * (192 + 8)) * 4;  // 104448
    constexpr int SMEM2 = 3 * (64 * 36 + 32 * (128 + 8)) * 4;  // 79872

    static bool attrs_set = false;
    if (!attrs_set) {
        cudaFuncSetAttribute(gemm_kernel<192>,
                             cudaFuncAttributeMaxDynamicSharedMemorySize, SMEM1);
        cudaFuncSetAttribute(gemm_kernel<128>,
                             cudaFuncAttributeMaxDynamicSharedMemorySize, SMEM2);
        cudaFuncSetAttribute(attn_kernel,
                             cudaFuncAttributeMaxDynamicSharedMemorySize, ATTN_SMEM_BYTES);
        attrs_set = true;
    }

    // k scale folded into gemm2 epilogue: 1/sqrt(128) * log2(e)
    const float KSCALE = 0.08838834764831845f * 1.4426950408889634f;

    // 0) pre-round all weights to tf32-rna (unbiased)
    prep_w<<<WR_TOT / 256, 256>>>(w_dkv, w_q, w_k, w_v);

    // 1) latent = x@w_dkv -> d_out latent (fp32); q = x@w_q -> qT (transposed, rna)
    gemm_kernel<192><<<dim3(1, M_TOTAL / 64), 256, SMEM1>>>(
        x, wr + WR_DKV, wr + WR_Q, latent, qTp, E_DIM, L_DIM, H_DIM, 0, 1.f, 1);

    // 2) k = latent@w_k (scaled), v = latent@w_v -> scratch, rna on store
    gemm_kernel<128><<<dim3(2, M_TOTAL / 64), 256, SMEM2>>>(
        latent, wr + WR_K, wr + WR_V, kp, vp, L_DIM, H_DIM, H_DIM, 1, KSCALE, 0);

    // 3) causal flash attention (512 CTAs, 3/SM, longest-first)
    attn_kernel<<<512, 128, ATTN_SMEM_BYTES>>>(qTp, kp, vp, out);
}

// round 11
// speedup vs baseline: 1.2795x; 1.2795x over previous
#include <cuda_runtime.h>
#include <cstdint>

#define M_TOTAL 32768
#define E_DIM 2048
#define L_DIM 64
#define H_DIM 128
#define S_LEN 4096

// Scratch (device globals: allocation-free rule)
__device__ float g_q[(size_t)M_TOTAL * H_DIM];
__device__ float g_k[(size_t)M_TOTAL * H_DIM];
__device__ float g_v[(size_t)M_TOTAL * H_DIM];

// Pre-rounded (tf32-rna) weights, same layouts as inputs:
#define WR_DKV 0
#define WR_Q   (2048 * 64)
#define WR_K   (WR_Q + 2048 * 128)
#define WR_V   (WR_K + 64 * 128)
#define WR_TOT (WR_V + 64 * 128)
__device__ float g_wr[WR_TOT];

// ---------------- tf32 / async helpers ----------------

__device__ __forceinline__ void mma_tf32(float* d, const uint32_t* a, const uint32_t* b) {
    asm volatile(
        "mma.sync.aligned.m16n8k8.row.col.f32.tf32.tf32.f32 "
        "{%0,%1,%2,%3}, {%4,%5,%6,%7}, {%8,%9}, {%0,%1,%2,%3};\n"
        : "+f"(d[0]), "+f"(d[1]), "+f"(d[2]), "+f"(d[3])
        : "r"(a[0]), "r"(a[1]), "r"(a[2]), "r"(a[3]), "r"(b[0]), "r"(b[1]));
}

__device__ __forceinline__ uint32_t to_tf32(float x) {
    uint32_t h;
    asm("cvt.rna.tf32.f32 %0, %1;" : "=r"(h) : "f"(x));
    return h;
}

__device__ __forceinline__ void cp16(void* dst, const void* src) {
    uint32_t d = (uint32_t)__cvta_generic_to_shared(dst);
    asm volatile("cp.async.cg.shared.global [%0], [%1], 16;\n" :: "r"(d), "l"(src));
}
#define CP_COMMIT asm volatile("cp.async.commit_group;\n")
#define CP_WAIT0  asm volatile("cp.async.wait_group 0;\n")
#define CP_WAIT1  asm volatile("cp.async.wait_group 1;\n")
#define CP_WAIT2  asm volatile("cp.async.wait_group 2;\n")

// k scale folded into the fused epilogue: 1/sqrt(128) * log2(e)
#define KSCALE_C (0.08838834764831845f * 1.4426950408889634f)

// ---------------- weight pre-rounding (once per call, ~5us) ----------------

__global__ void prep_w(const float* __restrict__ w_dkv, const float* __restrict__ w_q,
                       const float* __restrict__ w_k, const float* __restrict__ w_v) {
    int i = blockIdx.x * 256 + threadIdx.x;
    float v;
    if (i < WR_Q)       v = w_dkv[i];
    else if (i < WR_K)  v = w_q[i - WR_Q];
    else if (i < WR_V)  v = w_k[i - WR_K];
    else                v = w_v[i - WR_V];
    g_wr[i] = __uint_as_float(to_tf32(v));
}

// ---------------- fused GEMM1 + k/v decompress ----------------
// Main loop: [latent(64) | q(128)] = x[M,2048] @ [w_dkv|w_q] (1xTF32, 3-stage
// cp.async). Epilogue: latent kept in smem; k = latent@w_k (KSCALE, rna),
// v = latent@w_v (rna) computed in-CTA from pre-rounded weights staged into
// the dead pipeline buffers. BM=64, 256 threads = 8 warps 2(m) x 4(n).

constexpr int G_BN = 192;
constexpr int G_KT = 32;
constexpr int G_ASTR = 36;
constexpr int G_BSTR = G_BN + 8;              // 200
constexpr int G_ASZ = 64 * G_ASTR;            // 2304
constexpr int G_BSZ = G_KT * G_BSTR;          // 6400
constexpr int G_BUF = G_ASZ + G_BSZ;          // 8704 floats
constexpr int G_SMEM = 3 * G_BUF * 4;         // 104448 bytes
// epilogue overlays (within the 3*G_BUF float region):
constexpr int WSTR = 264;                     // weights stride (256+8)
constexpr int EP_WS = 0;                      // Ws: 64 x 264 = 16896 floats
constexpr int EP_LS = 64 * WSTR;              // Ls: 64 x 68  = 4352 floats
constexpr int LSTR = 68;
static_assert(EP_LS + 64 * LSTR <= 3 * G_BUF, "epilogue overlay fits");

__global__ void __launch_bounds__(256, 2) gemm1_fused(
    const float* __restrict__ A,
    const float* __restrict__ wr,
    float* __restrict__ latent, float* __restrict__ qout,
    float* __restrict__ kout, float* __restrict__ vout)
{
    extern __shared__ float sh[];

    const int tid = threadIdx.x;
    const int warp = tid >> 5, lane = tid & 31;
    const int wm = warp >> 2;               // 0..1 (32 rows)
    const int wn = warp & 3;                // 0..3 (48 cols main / 64 cols epi)
    const int lr = lane >> 2, lc = lane & 3;
    const int m0 = blockIdx.x * 64;

    const int arow = tid >> 2;              // 0..63
    const int ac4 = (tid & 3) * 4;

    const float* B1 = wr + WR_DKV;          // [2048 x 64]
    const float* B2 = wr + WR_Q;            // [2048 x 128]

    float acc[2][6][4];
#pragma unroll
    for (int mt = 0; mt < 2; mt++)
#pragma unroll
        for (int nt = 0; nt < 6; nt++)
#pragma unroll
            for (int j = 0; j < 4; j++) acc[mt][nt][j] = 0.f;

    const int nk = E_DIM / G_KT;            // 64

    auto stage = [&](int kt) {
        float* As = sh + (kt % 3) * G_BUF;
        float* Bs = As + G_ASZ;
        int kb = kt * G_KT;
        cp16(&As[arow * G_ASTR + ac4],      A + (size_t)(m0 + arow) * E_DIM + kb + ac4);
        cp16(&As[arow * G_ASTR + ac4 + 16], A + (size_t)(m0 + arow) * E_DIM + kb + ac4 + 16);
        constexpr int NB = (G_KT * G_BN / 4) / 256;  // 6
#pragma unroll
        for (int it = 0; it < NB; it++) {
            int i = it * 256 + tid;
            int brow = i / (G_BN / 4);
            int bc4 = (i % (G_BN / 4)) * 4;
            const float* src = (bc4 < 64) ? (B1 + (size_t)(kb + brow) * L_DIM + bc4)
                                          : (B2 + (size_t)(kb + brow) * H_DIM + (bc4 - 64));
            cp16(&Bs[brow * G_BSTR + bc4], src);
        }
        CP_COMMIT;
    };

    stage(0);
    stage(1);

    for (int kt = 0; kt < nk; kt++) {
        if (kt + 2 < nk) { stage(kt + 2); CP_WAIT2; }
        else if (kt + 1 < nk) CP_WAIT1;
        else CP_WAIT0;
        __syncthreads();

        const float* As = sh + (kt % 3) * G_BUF;
        const float* Bs = As + G_ASZ;

#pragma unroll
        for (int ks = 0; ks < 4; ks++) {
            uint32_t ah[2][4];
#pragma unroll
            for (int mt = 0; mt < 2; mt++) {
                int rb = wm * 32 + mt * 16;
                ah[mt][0] = to_tf32(As[(rb + lr) * G_ASTR + ks * 8 + lc]);
                ah[mt][1] = to_tf32(As[(rb + lr + 8) * G_ASTR + ks * 8 + lc]);
                ah[mt][2] = to_tf32(As[(rb + lr) * G_ASTR + ks * 8 + lc + 4]);
                ah[mt][3] = to_tf32(As[(rb + lr + 8) * G_ASTR + ks * 8 + lc + 4]);
            }
#pragma unroll
            for (int nt = 0; nt < 6; nt++) {
                int c0 = wn * 48 + nt * 8 + lr;
                uint32_t bh[2];
                bh[0] = __float_as_uint(Bs[(ks * 8 + lc) * G_BSTR + c0]);
                bh[1] = __float_as_uint(Bs[(ks * 8 + lc + 4) * G_BSTR + c0]);
#pragma unroll
                for (int mt = 0; mt < 2; mt++)
                    mma_tf32(acc[mt][nt], ah[mt], bh);
            }
        }
        __syncthreads();
    }

    // ---- epilogue: stage w_k|w_v into dead pipeline smem (overlapped) ----
    {
        float* Ws = sh + EP_WS;
#pragma unroll
        for (int it = 0; it < 16; it++) {
            int i = it * 256 + tid;          // 0..4095
            int row = i >> 6;                // 0..63
            int c4 = (i & 63) * 4;           // 0..252
            const float* src = (c4 < 128) ? (wr + WR_K + (size_t)row * H_DIM + c4)
                                          : (wr + WR_V + (size_t)row * H_DIM + (c4 - 128));
            cp16(&Ws[row * WSTR + c4], src);
        }
        CP_COMMIT;
    }

    // ---- store latent (d_out + smem) and q (gmem), from acc ----
    {
        float* Ls = sh + EP_LS;
#pragma unroll
        for (int mt = 0; mt < 2; mt++) {
            int rloc = wm * 32 + mt * 16 + lr;
            int r0 = m0 + rloc;
#pragma unroll
            for (int nt = 0; nt < 6; nt++) {
                int gc = wn * 48 + nt * 8 + lc * 2;
                float2 v01 = make_float2(acc[mt][nt][0], acc[mt][nt][1]);
                float2 v23 = make_float2(acc[mt][nt][2], acc[mt][nt][3]);
                if (gc < 64) {
                    *(float2*)(latent + (size_t)r0 * L_DIM + gc)       = v01;
                    *(float2*)(latent + (size_t)(r0 + 8) * L_DIM + gc) = v23;
                    *(float2*)&Ls[rloc * LSTR + gc]       = v01;
                    *(float2*)&Ls[(rloc + 8) * LSTR + gc] = v23;
                } else {
                    *(float2*)(qout + (size_t)r0 * H_DIM + gc - 64)       = v01;
                    *(float2*)(qout + (size_t)(r0 + 8) * H_DIM + gc - 64) = v23;
                }
            }
        }
    }
    CP_WAIT0;
    __syncthreads();

    // ---- k|v = latent @ [w_k|w_v] : warp = 32 rows (2mt) x 64 cols (8nt) ----
    {
        const float* Ws = sh + EP_WS;
        const float* Ls = sh + EP_LS;
        float acc2[2][8][4];
#pragma unroll
        for (int mt = 0; mt < 2; mt++)
#pragma unroll
            for (int nt = 0; nt < 8; nt++)
#pragma unroll
                for (int j = 0; j < 4; j++) acc2[mt][nt][j] = 0.f;

#pragma unroll
        for (int ks = 0; ks < 8; ks++) {
            uint32_t ah[2][4];
#pragma unroll
            for (int mt = 0; mt < 2; mt++) {
                int rb = wm * 32 + mt * 16;
                ah[mt][0] = to_tf32(Ls[(rb + lr) * LSTR + ks * 8 + lc]);
                ah[mt][1] = to_tf32(Ls[(rb + lr + 8) * LSTR + ks * 8 + lc]);
                ah[mt][2] = to_tf32(Ls[(rb + lr) * LSTR + ks * 8 + lc + 4]);
                ah[mt][3] = to_tf32(Ls[(rb + lr + 8) * LSTR + ks * 8 + lc + 4]);
            }
#pragma unroll
            for (int nt = 0; nt < 8; nt++) {
                int c0 = wn * 64 + nt * 8 + lr;
                uint32_t bh[2];
                bh[0] = __float_as_uint(Ws[(ks * 8 + lc) * WSTR + c0]);
                bh[1] = __float_as_uint(Ws[(ks * 8 + lc + 4) * WSTR + c0]);
#pragma unroll
                for (int mt = 0; mt < 2; mt++)
                    mma_tf32(acc2[mt][nt], ah[mt], bh);
            }
        }

        // store k (scaled, rna) / v (rna)
#pragma unroll
        for (int mt = 0; mt < 2; mt++) {
            int r0 = m0 + wm * 32 + mt * 16 + lr;
#pragma unroll
            for (int nt = 0; nt < 8; nt++) {
                int gc = wn * 64 + nt * 8 + lc * 2;
                float* dst;
                int col;
                float cs;
                if (gc < 128) { dst = kout; col = gc;       cs = KSCALE_C; }
                else          { dst = vout; col = gc - 128; cs = 1.f; }
                float o0 = __uint_as_float(to_tf32(acc2[mt][nt][0] * cs));
                float o1 = __uint_as_float(to_tf32(acc2[mt][nt][1] * cs));
                float o2 = __uint_as_float(to_tf32(acc2[mt][nt][2] * cs));
                float o3 = __uint_as_float(to_tf32(acc2[mt][nt][3] * cs));
                *(float2*)(dst + (size_t)r0 * H_DIM + col)       = make_float2(o0, o1);
                *(float2*)(dst + (size_t)(r0 + 8) * H_DIM + col) = make_float2(o2, o3);
            }
        }
    }
}

// ---------------- Flash attention (causal), LDS-byte-optimized (R9) ----------------
// BLOCK_M=64, 4 warps = (wm: 32-row half) x (wn: 32-kv-col half for QK /
// 64-head-col half for PV). q mt0 in regs, mt1 from smem Q. P aliases Ks.
// k pre-scaled by 1/sqrt(128)*log2e; softmax in exp2 domain. QK/PV: 1xTF32.

constexpr int AKS = 132;
constexpr int AVS = 136;
constexpr int APS = 68;                 // P stride (aliased in Ks region)
constexpr int VOFF = 64 * AKS;          // 8448
constexpr int XOFF = VOFF + 64 * AVS;   // 17152 (exchange buffer, 128 floats)
constexpr int QOFF = XOFF + 128;        // 17280
constexpr int ATTN_SMEM_BYTES = (QOFF + 64 * 132) * 4;   // 102912

__global__ void __launch_bounds__(128, 2) attn_kernel(
    const float* __restrict__ q, const float* __restrict__ k,
    const float* __restrict__ v, float* __restrict__ out)
{
    extern __shared__ float sm[];
    float* Ks = sm;                 // K tile; later aliased as P (stride APS)
    float* Vs = sm + VOFF;
    float* Xb = sm + XOFF;
    float* Qs = sm + QOFF;

    const int idx = blockIdx.x;
    const int b = idx & 7;
    const int qb = 63 - (idx >> 3);         // longest first
    const int tid = threadIdx.x;
    const int warp = tid >> 5, lane = tid & 31;
    const int lr = lane >> 2, lc = lane & 3;
    const int wm = warp >> 1;               // row half (32 rows)
    const int wn = warp & 1;                // kv half (QK) / head half (PV)

    const float* qB = q + (size_t)b * S_LEN * H_DIM;
    const float* kB = k + (size_t)b * S_LEN * H_DIM;
    const float* vB = v + (size_t)b * S_LEN * H_DIM;

    const int row64 = tid >> 5;
    const int c4 = (tid & 31) * 4;

    // Stage Q tile (64 x 128) once
#pragma unroll
    for (int rnd = 0; rnd < 16; rnd++) {
        int row = row64 + rnd * 4;
        cp16(&Qs[row * 132 + c4], qB + (size_t)(qb * 64 + row) * H_DIM + c4);
    }
    CP_COMMIT;

    // q mt0 fragments rna-rounded in regs (k carries the softmax scale)
    const int qrow0 = qb * 64 + wm * 32 + lr;
    uint32_t qr[64];
#pragma unroll
    for (int ks = 0; ks < 16; ks++) {
        int c = ks * 8 + lc;
        qr[ks * 4 + 0] = to_tf32(qB[(size_t)qrow0 * H_DIM + c]);
        qr[ks * 4 + 1] = to_tf32(qB[(size_t)(qrow0 + 8) * H_DIM + c]);
        qr[ks * 4 + 2] = to_tf32(qB[(size_t)qrow0 * H_DIM + c + 4]);
        qr[ks * 4 + 3] = to_tf32(qB[(size_t)(qrow0 + 8) * H_DIM + c + 4]);
    }

    float acc[2][8][4];
#pragma unroll
    for (int mt = 0; mt < 2; mt++)
#pragma unroll
        for (int nt = 0; nt < 8; nt++)
#pragma unroll
            for (int j = 0; j < 4; j++) acc[mt][nt][j] = 0.f;
    float mrow[2][2] = {{-INFINITY, -INFINITY}, {-INFINITY, -INFINITY}};
    float lrow[2][2] = {{0.f, 0.f}, {0.f, 0.f}};

    for (int kv = 0; kv <= qb; kv++) {
        __syncthreads();  // (1) Ks(P)/Vs dead

        // stage K,V tile (64 x 128 each)
#pragma unroll
        for (int rnd = 0; rnd < 16; rnd++) {
            int row = row64 + rnd * 4;
            cp16(&Ks[row * AKS + c4], kB + (size_t)(kv * 64 + row) * H_DIM + c4);
            cp16(&Vs[row * AVS + c4], vB + (size_t)(kv * 64 + row) * H_DIM + c4);
        }
        CP_COMMIT;
        CP_WAIT0;
        __syncthreads();  // (2) tiles ready

        // ---- S = q @ k^T : rows 32*wm (2mt) x kv cols 32*wn (4nt), 1xTF32 ----
        float sc[2][4][4];
#pragma unroll
        for (int mt = 0; mt < 2; mt++)
#pragma unroll
            for (int nt = 0; nt < 4; nt++)
#pragma unroll
                for (int j = 0; j < 4; j++) sc[mt][nt][j] = 0.f;

        const int q1row = wm * 32 + 16 + lr;
#pragma unroll
        for (int ks = 0; ks < 16; ks++) {
            uint32_t q1[4];
            q1[0] = to_tf32(Qs[q1row * 132 + ks * 8 + lc]);
            q1[1] = to_tf32(Qs[(q1row + 8) * 132 + ks * 8 + lc]);
            q1[2] = to_tf32(Qs[q1row * 132 + ks * 8 + lc + 4]);
            q1[3] = to_tf32(Qs[(q1row + 8) * 132 + ks * 8 + lc + 4]);
#pragma unroll
            for (int nt = 0; nt < 4; nt++) {
                int kr = wn * 32 + nt * 8 + lr;
                uint32_t bh[2];
                bh[0] = __float_as_uint(Ks[kr * AKS + ks * 8 + lc]);
                bh[1] = __float_as_uint(Ks[kr * AKS + ks * 8 + lc + 4]);
                mma_tf32(sc[0][nt], &qr[ks * 4], bh);
                mma_tf32(sc[1][nt], q1, bh);
            }
        }

        // Diagonal-block causal mask (tile-local coords)
        if (kv == qb) {
#pragma unroll
            for (int mt = 0; mt < 2; mt++)
#pragma unroll
                for (int nt = 0; nt < 4; nt++)
#pragma unroll
                    for (int j = 0; j < 4; j++) {
                        int col = wn * 32 + nt * 8 + lc * 2 + (j & 1);
                        int row = wm * 32 + mt * 16 + lr + (j >> 1) * 8;
                        if (col > row) sc[mt][nt][j] = -INFINITY;
                    }
        }

        // ---- online softmax (exp2 domain, cross-warp over wn) ----
        float mnew[2][2] = {{-INFINITY, -INFINITY}, {-INFINITY, -INFINITY}};
#pragma unroll
        for (int mt = 0; mt < 2; mt++)
#pragma unroll
            for (int nt = 0; nt < 4; nt++)
#pragma unroll
                for (int j = 0; j < 4; j++)
                    mnew[mt][j >> 1] = fmaxf(mnew[mt][j >> 1], sc[mt][nt][j]);
#pragma unroll
        for (int off = 1; off < 4; off <<= 1)
#pragma unroll
            for (int mt = 0; mt < 2; mt++) {
                mnew[mt][0] = fmaxf(mnew[mt][0], __shfl_xor_sync(0xffffffffu, mnew[mt][0], off));
                mnew[mt][1] = fmaxf(mnew[mt][1], __shfl_xor_sync(0xffffffffu, mnew[mt][1], off));
            }
        if (lc == 0) {
#pragma unroll
            for (int mt = 0; mt < 2; mt++)
#pragma unroll
                for (int h = 0; h < 2; h++)
                    Xb[((wm * 2 + wn) * 4 + mt * 2 + h) * 8 + lr] = mnew[mt][h];
        }
        __syncthreads();  // (3) m-exchange

        float alpha[2][2];
#pragma unroll
        for (int mt = 0; mt < 2; mt++)
#pragma unroll
            for (int h = 0; h < 2; h++) {
                float mo = Xb[((wm * 2 + (1 - wn)) * 4 + mt * 2 + h) * 8 + lr];
                float mt_ = fmaxf(fmaxf(mrow[mt][h], mnew[mt][h]), mo);
                alpha[mt][h] = exp2f(mrow[mt][h] - mt_);
                mrow[mt][h] = mt_;
            }

        float rs[2][2] = {{0.f, 0.f}, {0.f, 0.f}};
#pragma unroll
        for (int mt = 0; mt < 2; mt++)
#pragma unroll
            for (int nt = 0; nt < 4; nt++)
#pragma unroll
                for (int j = 0; j < 4; j++) {
                    float p = exp2f(sc[mt][nt][j] - mrow[mt][j >> 1]);
                    sc[mt][nt][j] = p;
                    rs[mt][j >> 1] += p;
                }
#pragma unroll
        for (int off = 1; off < 4; off <<= 1)
#pragma unroll
            for (int mt = 0; mt < 2; mt++) {
                rs[mt][0] += __shfl_xor_sync(0xffffffffu, rs[mt][0], off);
                rs[mt][1] += __shfl_xor_sync(0xffffffffu, rs[mt][1], off);
            }

        // write P (rna) into dead Ks region; write rs partials
#pragma unroll
        for (int mt = 0; mt < 2; mt++)
#pragma unroll
            for (int nt = 0; nt < 4; nt++)
#pragma unroll
                for (int j = 0; j < 4; j++) {
                    int row = wm * 32 + mt * 16 + lr + (j >> 1) * 8;
                    int col = wn * 32 + nt * 8 + lc * 2 + (j & 1);
                    Ks[row * APS + col] = __uint_as_float(to_tf32(sc[mt][nt][j]));
                }
        if (lc == 0) {
#pragma unroll
            for (int mt = 0; mt < 2; mt++)
#pragma unroll
                for (int h = 0; h < 2; h++)
                    Xb[64 + ((wm * 2 + wn) * 4 + mt * 2 + h) * 8 + lr] = rs[mt][h];
        }
        __syncthreads();  // (4) P + rs ready

#pragma unroll
        for (int mt = 0; mt < 2; mt++)
#pragma unroll
            for (int h = 0; h < 2; h++) {
                float ro = Xb[64 + ((wm * 2 + (1 - wn)) * 4 + mt * 2 + h) * 8 + lr];
                lrow[mt][h] = lrow[mt][h] * alpha[mt][h] + rs[mt][h] + ro;
            }

#pragma unroll
        for (int mt = 0; mt < 2; mt++)
#pragma unroll
            for (int nt = 0; nt < 8; nt++) {
                acc[mt][nt][0] *= alpha[mt][0]; acc[mt][nt][1] *= alpha[mt][0];
                acc[mt][nt][2] *= alpha[mt][1]; acc[mt][nt][3] *= alpha[mt][1];
            }

        // ---- O += P @ V : rows 32*wm (2mt) x head cols 64*wn (8nt2), 1xTF32 ----
#pragma unroll
        for (int ks2 = 0; ks2 < 8; ks2++) {
            uint32_t pa[2][4];
#pragma unroll
            for (int mt = 0; mt < 2; mt++) {
                int base = wm * 32 + mt * 16;
                pa[mt][0] = __float_as_uint(Ks[(base + lr) * APS + ks2 * 8 + lc]);
                pa[mt][1] = __float_as_uint(Ks[(base + lr + 8) * APS + ks2 * 8 + lc]);
                pa[mt][2] = __float_as_uint(Ks[(base + lr) * APS + ks2 * 8 + lc + 4]);
                pa[mt][3] = __float_as_uint(Ks[(base + lr + 8) * APS + ks2 * 8 + lc + 4]);
            }
#pragma unroll
            for (int nt2 = 0; nt2 < 8; nt2++) {
                int vc = wn * 64 + nt2 * 8 + lr;
                uint32_t vb[2];
                vb[0] = __float_as_uint(Vs[(ks2 * 8 + lc) * AVS + vc]);
                vb[1] = __float_as_uint(Vs[(ks2 * 8 + lc + 4) * AVS + vc]);
                mma_tf32(acc[0][nt2], pa[0], vb);
                mma_tf32(acc[1][nt2], pa[1], vb);
            }
        }
    }

    // Epilogue
#pragma unroll
    for (int mt = 0; mt < 2; mt++) {
        float inv0 = 1.f / lrow[mt][0];
        float inv1 = 1.f / lrow[mt][1];
        size_t rowg = (size_t)b * S_LEN + qb * 64 + wm * 32 + mt * 16 + lr;
#pragma unroll
        for (int nt2 = 0; nt2 < 8; nt2++) {
            int col = wn * 64 + nt2 * 8 + lc * 2;
            *(float2*)(out + rowg * H_DIM + col) =
                make_float2(acc[mt][nt2][0] * inv0, acc[mt][nt2][1] * inv0);
            *(float2*)(out + (rowg + 8) * H_DIM + col) =
                make_float2(acc[mt][nt2][2] * inv1, acc[mt][nt2][3] * inv1);
        }
    }
}

// ---------------- launch ----------------

extern "C" void kernel_launch(void* const* d_in, const int* in_sizes, int n_in,
                              void* d_out, int out_size) {
    const float* x     = (const float*)d_in[0];
    const float* w_dkv = (const float*)d_in[1];
    const float* w_k   = (const float*)d_in[2];
    const float* w_v   = (const float*)d_in[3];
    const float* w_q   = (const float*)d_in[4];

    float* out = (float*)d_out;                          // [B,S,HEAD]
    float* latent = out + (size_t)M_TOTAL * H_DIM;       // [B,S,LATENT]

    float *qp, *kp, *vp, *wr;
    cudaGetSymbolAddress((void**)&qp, g_q);
    cudaGetSymbolAddress((void**)&kp, g_k);
    cudaGetSymbolAddress((void**)&vp, g_v);
    cudaGetSymbolAddress((void**)&wr, g_wr);

    static bool attrs_set = false;
    if (!attrs_set) {
        cudaFuncSetAttribute(gemm1_fused,
                             cudaFuncAttributeMaxDynamicSharedMemorySize, G_SMEM);
        cudaFuncSetAttribute(attn_kernel,
                             cudaFuncAttributeMaxDynamicSharedMemorySize, ATTN_SMEM_BYTES);
        attrs_set = true;
    }

    // 0) pre-round all weights to tf32-rna (unbiased)
    prep_w<<<WR_TOT / 256, 256>>>(w_dkv, w_q, w_k, w_v);

    // 1) fused: latent -> d_out; q -> scratch; k (scaled, rna), v (rna) -> scratch
    gemm1_fused<<<M_TOTAL / 64, 256, G_SMEM>>>(x, wr, latent, qp, kp, vp);

    // 2) causal flash attention (512 CTAs, 2/SM, longest-first)
    attn_kernel<<<512, 128, ATTN_SMEM_BYTES>>>(qp, kp, vp, out);
}